// round 2
// baseline (speedup 1.0000x reference)
#include <cuda_runtime.h>
#include <cuda_bf16.h>
#include <math.h>

// Problem constants
#define BB   4
#define SS   1024
#define DIN  256
#define VV   256
#define KDIM 64
#define HH   8
#define TT   4
#define BS   (BB*SS)          // 4096
#define NCH  32               // row chunks for BN stats (4096/128)
#define EPS  1e-3f

// ---------------- scratch (device globals; no allocation allowed) -----------
__device__ float g_net[HH*BS*VV];            // 8*4096*256
__device__ float g_q[HH*BS*KDIM];
__device__ float g_k[HH*BS*KDIM];
__device__ float g_v[HH*BS*VV];
__device__ float g_scores[(size_t)HH*BB*SS*SS];  // 8*4*1024*1024 (134MB)
__device__ float g_attnout[HH*BS*VV];
__device__ float g_z[HH*BS*VV];
__device__ float g_part[HH*NCH*VV*2];

// ---------------- tiled fp32 GEMM, C = alpha * A @ B  (row-major) -----------
#define BM 64
#define BN 64
#define BK 16

__global__ void gemm_nn(const float* __restrict__ A, const float* __restrict__ B,
                        float* __restrict__ C, int M, int N, int K,
                        long long sA, long long sB, long long sC,
                        float alpha, int rep, long long repStride)
{
    A += (long long)blockIdx.z * sA;
    B += (long long)blockIdx.z * sB;
    C += (long long)blockIdx.z * sC;
    const int m0 = blockIdx.y * BM, n0 = blockIdx.x * BN;
    __shared__ float As[BK][BM+1];
    __shared__ float Bs[BK][BN+1];
    const int tx = threadIdx.x, ty = threadIdx.y;
    const int tid = ty*16 + tx;
    const int ka = tid % BK, ia = tid / BK;    // A loader: k fastest (coalesced 16-wide)
    const int jb = tid % BN, kb = tid / BN;    // B loader: n fastest (coalesced 64-wide)
    float acc[4][4] = {};
    for (int k0 = 0; k0 < K; k0 += BK) {
        #pragma unroll
        for (int l = 0; l < 4; l++)
            As[ka][ia + l*16] = A[(size_t)(m0 + ia + l*16)*K + (k0 + ka)];
        #pragma unroll
        for (int l = 0; l < 4; l++)
            Bs[kb + l*4][jb] = B[(size_t)(k0 + kb + l*4)*N + (n0 + jb)];
        __syncthreads();
        #pragma unroll
        for (int kk = 0; kk < BK; kk++) {
            float a[4], b[4];
            #pragma unroll
            for (int i = 0; i < 4; i++) a[i] = As[kk][ty*4 + i];
            #pragma unroll
            for (int j = 0; j < 4; j++) b[j] = Bs[kk][tx*4 + j];
            #pragma unroll
            for (int i = 0; i < 4; i++)
                #pragma unroll
                for (int j = 0; j < 4; j++)
                    acc[i][j] += a[i] * b[j];
        }
        __syncthreads();
    }
    #pragma unroll
    for (int i = 0; i < 4; i++)
        #pragma unroll
        for (int j = 0; j < 4; j++) {
            float v = acc[i][j] * alpha;
            size_t off = (size_t)(m0 + ty*4 + i)*N + (n0 + tx*4 + j);
            for (int r = 0; r < rep; r++)
                C[off + (size_t)r * repStride] = v;
        }
}

// C = alpha * A @ B^T   (B is [N,K] row-major)
__global__ void gemm_nt(const float* __restrict__ A, const float* __restrict__ B,
                        float* __restrict__ C, int M, int N, int K,
                        long long sA, long long sB, long long sC, float alpha)
{
    A += (long long)blockIdx.z * sA;
    B += (long long)blockIdx.z * sB;
    C += (long long)blockIdx.z * sC;
    const int m0 = blockIdx.y * BM, n0 = blockIdx.x * BN;
    __shared__ float As[BK][BM+1];
    __shared__ float Bs[BK][BN+1];
    const int tx = threadIdx.x, ty = threadIdx.y;
    const int tid = ty*16 + tx;
    const int ka = tid % BK, ia = tid / BK;
    const int kt = tid % BK, jt = tid / BK;    // B^T loader: k fastest
    float acc[4][4] = {};
    for (int k0 = 0; k0 < K; k0 += BK) {
        #pragma unroll
        for (int l = 0; l < 4; l++)
            As[ka][ia + l*16] = A[(size_t)(m0 + ia + l*16)*K + (k0 + ka)];
        #pragma unroll
        for (int l = 0; l < 4; l++)
            Bs[kt][jt + l*16] = B[(size_t)(n0 + jt + l*16)*K + (k0 + kt)];
        __syncthreads();
        #pragma unroll
        for (int kk = 0; kk < BK; kk++) {
            float a[4], b[4];
            #pragma unroll
            for (int i = 0; i < 4; i++) a[i] = As[kk][ty*4 + i];
            #pragma unroll
            for (int j = 0; j < 4; j++) b[j] = Bs[kk][tx*4 + j];
            #pragma unroll
            for (int i = 0; i < 4; i++)
                #pragma unroll
                for (int j = 0; j < 4; j++)
                    acc[i][j] += a[i] * b[j];
        }
        __syncthreads();
    }
    #pragma unroll
    for (int i = 0; i < 4; i++)
        #pragma unroll
        for (int j = 0; j < 4; j++)
            C[(size_t)(m0 + ty*4 + i)*N + (n0 + tx*4 + j)] = acc[i][j] * alpha;
}

// ---------------- softmax over rows of length 1024 ---------------------------
__global__ void softmax_rows(float* __restrict__ s)
{
    float* row = s + (size_t)blockIdx.x * SS;
    const int tid = threadIdx.x;
    __shared__ float red[256];
    float v[4];
    float m = -1e30f;
    #pragma unroll
    for (int i = 0; i < 4; i++) { v[i] = row[tid + i*256]; m = fmaxf(m, v[i]); }
    red[tid] = m; __syncthreads();
    for (int st = 128; st > 0; st >>= 1) {
        if (tid < st) red[tid] = fmaxf(red[tid], red[tid + st]);
        __syncthreads();
    }
    m = red[0]; __syncthreads();
    float sum = 0.f;
    #pragma unroll
    for (int i = 0; i < 4; i++) { v[i] = __expf(v[i] - m); sum += v[i]; }
    red[tid] = sum; __syncthreads();
    for (int st = 128; st > 0; st >>= 1) {
        if (tid < st) red[tid] += red[tid + st];
        __syncthreads();
    }
    const float inv = 1.f / red[0];
    #pragma unroll
    for (int i = 0; i < 4; i++) row[tid + i*256] = v[i] * inv;
}

// ---------------- y = a + (relu?)(b); partial column stats -------------------
__global__ void add_stats(const float* __restrict__ a, const float* __restrict__ b,
                          float* __restrict__ y, float* __restrict__ part, int relu)
{
    const int c = threadIdx.x;            // channel 0..255
    const int h = blockIdx.y;
    const int chunk = blockIdx.x;         // 0..31, 128 rows each
    const size_t base = (size_t)h * BS * VV;
    float sum = 0.f, sq = 0.f;
    const int r0 = chunk * 128;
    for (int r = r0; r < r0 + 128; r++) {
        size_t idx = base + (size_t)r * VV + c;
        float bv = b[idx];
        if (relu) bv = fmaxf(bv, 0.f);
        float yv = a[idx] + bv;
        y[idx] = yv;
        sum += yv; sq += yv * yv;
    }
    size_t p = ((size_t)(h*NCH + chunk)*VV + c) * 2;
    part[p + 0] = sum;
    part[p + 1] = sq;
}

// ---------------- batchnorm normalize (redundant partial reduce) -------------
__global__ void bn_norm(float* __restrict__ y, const float* __restrict__ part,
                        const float* __restrict__ gamma, const float* __restrict__ beta,
                        int gstride)
{
    const int c = threadIdx.x;
    const int h = blockIdx.y;
    const int chunk = blockIdx.x;
    const float* p = part + (size_t)h * NCH * VV * 2;
    float sum = 0.f, sq = 0.f;
    #pragma unroll
    for (int j = 0; j < NCH; j++) {
        sum += p[((size_t)j*VV + c)*2 + 0];
        sq  += p[((size_t)j*VV + c)*2 + 1];
    }
    const float mean = sum * (1.f / BS);
    const float var  = sq  * (1.f / BS) - mean * mean;
    const float inv  = rsqrtf(var + EPS);
    const float g = gamma[(size_t)h * gstride + c];
    const float b = beta [(size_t)h * gstride + c];
    const float sc = inv * g;
    const float sh = b - mean * sc;
    float* base = y + (size_t)h * BS * VV;
    const int r0 = chunk * 128;
    for (int r = r0; r < r0 + 128; r++) {
        size_t idx = (size_t)r * VV + c;
        base[idx] = base[idx] * sc + sh;
    }
}

// ---------------- [H][B*S][V] -> [B,S,H,V] -----------------------------------
__global__ void write_out(const float* __restrict__ net, float* __restrict__ out)
{
    const int h = blockIdx.y, row = blockIdx.x, c = threadIdx.x;
    out[((size_t)row * HH + h) * VV + c] =
        net[(size_t)h * BS * VV + (size_t)row * VV + c];
}

// ---------------- launcher ---------------------------------------------------
extern "C" void kernel_launch(void* const* d_in, const int* in_sizes, int n_in,
                              void* d_out, int out_size)
{
    const float* x     = (const float*)d_in[0];
    const float* W_in  = (const float*)d_in[1];
    const float* Wq    = (const float*)d_in[2];
    const float* Wk    = (const float*)d_in[3];
    const float* Wv    = (const float*)d_in[4];
    const float* Wd    = (const float*)d_in[5];
    const float* g1    = (const float*)d_in[6];
    const float* b1    = (const float*)d_in[7];
    const float* g2    = (const float*)d_in[8];
    const float* b2    = (const float*)d_in[9];
    float* out = (float*)d_out;

    float *net, *q, *k, *v, *scores, *attnout, *z, *part;
    cudaGetSymbolAddress((void**)&net,     g_net);
    cudaGetSymbolAddress((void**)&q,       g_q);
    cudaGetSymbolAddress((void**)&k,       g_k);
    cudaGetSymbolAddress((void**)&v,       g_v);
    cudaGetSymbolAddress((void**)&scores,  g_scores);
    cudaGetSymbolAddress((void**)&attnout, g_attnout);
    cudaGetSymbolAddress((void**)&z,       g_z);
    cudaGetSymbolAddress((void**)&part,    g_part);

    dim3 thr(16, 16);
    const float scale = 0.125f;   // KD^-0.5

    // net[h] = x @ W_in, replicated to all 8 heads
    gemm_nn<<<dim3(VV/BN, BS/BM, 1), thr>>>(x, W_in, net, BS, VV, DIN,
                                            0, 0, 0, 1.f, HH, (long long)BS*VV);

    for (int t = 0; t < TT; t++) {
        // q/k/v, batched over heads
        gemm_nn<<<dim3(KDIM/BN, BS/BM, HH), thr>>>(net, Wq + (size_t)t*VV*KDIM, q,
            BS, KDIM, VV, (long long)BS*VV, (long long)TT*VV*KDIM, (long long)BS*KDIM, 1.f, 1, 0);
        gemm_nn<<<dim3(KDIM/BN, BS/BM, HH), thr>>>(net, Wk + (size_t)t*VV*KDIM, k,
            BS, KDIM, VV, (long long)BS*VV, (long long)TT*VV*KDIM, (long long)BS*KDIM, 1.f, 1, 0);
        gemm_nn<<<dim3(VV/BN, BS/BM, HH), thr>>>(net, Wv + (size_t)t*VV*VV, v,
            BS, VV, VV, (long long)BS*VV, (long long)TT*VV*VV, (long long)BS*VV, 1.f, 1, 0);

        // scores = scale * q @ k^T, batched over (h,b) = 32
        gemm_nt<<<dim3(SS/BN, SS/BM, HH*BB), thr>>>(q, k, scores,
            SS, SS, KDIM, (long long)SS*KDIM, (long long)SS*KDIM, (long long)SS*SS, scale);

        softmax_rows<<<HH*BB*SS, 256>>>(scores);

        // attnout = scores @ v
        gemm_nn<<<dim3(VV/BN, SS/BM, HH*BB), thr>>>(scores, v, attnout,
            SS, VV, SS, (long long)SS*SS, (long long)SS*VV, (long long)SS*VV, 1.f, 1, 0);

        // net = BN(net + attnout; g1[t], b1[t])
        add_stats<<<dim3(NCH, HH), 256>>>(net, attnout, net, part, 0);
        bn_norm<<<dim3(NCH, HH), 256>>>(net, part, g1 + (size_t)t*VV, b1 + (size_t)t*VV, TT*VV);

        // z = net @ Wd; net = BN(net + relu(z); g2[t], b2[t])
        gemm_nn<<<dim3(VV/BN, BS/BM, HH), thr>>>(net, Wd + (size_t)t*VV*VV, z,
            BS, VV, VV, (long long)BS*VV, (long long)TT*VV*VV, (long long)BS*VV, 1.f, 1, 0);
        add_stats<<<dim3(NCH, HH), 256>>>(net, z, net, part, 1);
        bn_norm<<<dim3(NCH, HH), 256>>>(net, part, g2 + (size_t)t*VV, b2 + (size_t)t*VV, TT*VV);
    }

    write_out<<<dim3(BS, HH), 256>>>(net, out);
}

// round 5
// speedup vs baseline: 1.8654x; 1.8654x over previous
#include <cuda_runtime.h>
#include <cuda_bf16.h>
#include <math.h>

// Problem constants
#define BB   4
#define SS   1024
#define DIN  256
#define VV   256
#define KDIM 64
#define HH   8
#define TT   4
#define BS   (BB*SS)          // 4096
#define NCH  32               // row chunks for BN stats (4096/128)
#define EPS  1e-3f

// ---------------- scratch (device globals; no allocation allowed) -----------
__device__ float g_net[HH*BS*VV];
__device__ float g_q[HH*BS*KDIM];
__device__ float g_k[HH*BS*KDIM];
__device__ float g_v[HH*BS*VV];
__device__ float g_scores[(size_t)HH*BB*SS*SS];  // 134MB
__device__ float g_attnout[HH*BS*VV];
__device__ float g_z[HH*BS*VV];
__device__ float g_part[HH*NCH*VV*2];

// ---------------- TF32 helpers ----------------------------------------------
__device__ __forceinline__ unsigned f2tf(float f) {
    unsigned r;
    asm("cvt.rna.tf32.f32 %0, %1;" : "=r"(r) : "f"(f));
    return r;
}

// a = hi + lo decomposition for 3xTF32
__device__ __forceinline__ void split_tf32(float f, unsigned &hi, unsigned &lo) {
    hi = f2tf(f);
    lo = f2tf(f - __uint_as_float(hi));
}

__device__ __forceinline__ void mma_tf32(float c[4],
                                         const unsigned a[4],
                                         const unsigned b[2]) {
    asm volatile(
        "mma.sync.aligned.m16n8k8.row.col.f32.tf32.tf32.f32 "
        "{%0,%1,%2,%3}, {%4,%5,%6,%7}, {%8,%9}, {%0,%1,%2,%3};"
        : "+f"(c[0]), "+f"(c[1]), "+f"(c[2]), "+f"(c[3])
        : "r"(a[0]), "r"(a[1]), "r"(a[2]), "r"(a[3]), "r"(b[0]), "r"(b[1]));
}

// ---------------- 3xTF32 tensor-core GEMM, C = alpha * A @ op(B) -------------
// BM=128, BN=64, BK=32; 256 threads, 8 warps (4m x 2n), warp tile 32x32.
// NT=0: B is [K,N] row-major (C = A@B).  NT=1: B is [N,K] row-major (C = A@B^T).
#define GBM 128
#define GBN 64
#define GBK 32
#define ASTR 36        // A smem row stride (u32)
#define BSTR_NN 72
#define BSTR_NT 36
#define A_TILE (GBM*ASTR)   // 4608 u32
#define B_TILE 2304         // u32
#define SMEM_U32 (2*A_TILE + 2*B_TILE)   // 13824 u32 = 55296 B

template<int NT>
__global__ void __launch_bounds__(256)
gemm_mma(const float* __restrict__ A, const float* __restrict__ B,
         float* __restrict__ C, int M, int N, int K,
         long long sA, long long sB, long long sC,
         float alpha, int rep, long long repStride)
{
    A += (long long)blockIdx.z * sA;
    B += (long long)blockIdx.z * sB;
    C += (long long)blockIdx.z * sC;

    extern __shared__ unsigned smem[];
    unsigned* AsH = smem;
    unsigned* AsL = smem + A_TILE;
    unsigned* BsH = smem + 2*A_TILE;
    unsigned* BsL = smem + 2*A_TILE + B_TILE;

    const int t    = threadIdx.x;
    const int lane = t & 31;
    const int wid  = t >> 5;
    const int gid  = lane >> 2;   // groupID
    const int tig  = lane & 3;    // threadID_in_group
    const int wm   = (wid & 3) * 32;
    const int wn   = (wid >> 2) * 32;
    const int m0 = blockIdx.y * GBM, n0 = blockIdx.x * GBN;

    float acc[2][4][4] = {};

    for (int k0 = 0; k0 < K; k0 += GBK) {
        // ---- global loads to registers (float4) ----
        float4 ar[4];
        #pragma unroll
        for (int i = 0; i < 4; i++) {
            int idx = t + i * 256;            // 1024 float4 for A tile
            int r = idx >> 3, c4 = (idx & 7) << 2;
            ar[i] = *(const float4*)&A[(size_t)(m0 + r) * K + k0 + c4];
        }
        float4 br[2];
        #pragma unroll
        for (int i = 0; i < 2; i++) {
            int idx = t + i * 256;            // 512 float4 for B tile
            if (NT) {
                int r = idx >> 3, c4 = (idx & 7) << 2;   // r: n-row, c4: k
                br[i] = *(const float4*)&B[(size_t)(n0 + r) * K + k0 + c4];
            } else {
                int r = idx >> 4, c4 = (idx & 15) << 2;  // r: k-row, c4: n
                br[i] = *(const float4*)&B[(size_t)(k0 + r) * N + n0 + c4];
            }
        }
        __syncthreads();
        // ---- split & store to smem ----
        #pragma unroll
        for (int i = 0; i < 4; i++) {
            int idx = t + i * 256;
            int r = idx >> 3, c4 = (idx & 7) << 2;
            unsigned* ph = &AsH[r * ASTR + c4];
            unsigned* pl = &AsL[r * ASTR + c4];
            split_tf32(ar[i].x, ph[0], pl[0]);
            split_tf32(ar[i].y, ph[1], pl[1]);
            split_tf32(ar[i].z, ph[2], pl[2]);
            split_tf32(ar[i].w, ph[3], pl[3]);
        }
        #pragma unroll
        for (int i = 0; i < 2; i++) {
            int idx = t + i * 256;
            int off;
            if (NT) { int r = idx >> 3, c4 = (idx & 7) << 2;  off = r * BSTR_NT + c4; }
            else    { int r = idx >> 4, c4 = (idx & 15) << 2; off = r * BSTR_NN + c4; }
            unsigned* ph = &BsH[off];
            unsigned* pl = &BsL[off];
            split_tf32(br[i].x, ph[0], pl[0]);
            split_tf32(br[i].y, ph[1], pl[1]);
            split_tf32(br[i].z, ph[2], pl[2]);
            split_tf32(br[i].w, ph[3], pl[3]);
        }
        __syncthreads();

        // ---- 4 k-steps of m16n8k8, 3xTF32 ----
        #pragma unroll
        for (int ks = 0; ks < 4; ks++) {
            const int kk = ks * 8;
            unsigned aH[2][4], aL[2][4];
            #pragma unroll
            for (int i = 0; i < 2; i++) {
                const int mr = wm + i * 16;
                const int o0 = (mr + gid    ) * ASTR + kk + tig;
                const int o1 = (mr + gid + 8) * ASTR + kk + tig;
                aH[i][0] = AsH[o0];     aL[i][0] = AsL[o0];
                aH[i][1] = AsH[o1];     aL[i][1] = AsL[o1];
                aH[i][2] = AsH[o0 + 4]; aL[i][2] = AsL[o0 + 4];
                aH[i][3] = AsH[o1 + 4]; aL[i][3] = AsL[o1 + 4];
            }
            unsigned bH[4][2], bL[4][2];
            #pragma unroll
            for (int j = 0; j < 4; j++) {
                const int nc = wn + j * 8 + gid;
                int o0, o1;
                if (NT) { o0 = nc * BSTR_NT + kk + tig;  o1 = o0 + 4; }
                else    { o0 = (kk + tig) * BSTR_NN + nc; o1 = o0 + 4 * BSTR_NN; }
                bH[j][0] = BsH[o0]; bL[j][0] = BsL[o0];
                bH[j][1] = BsH[o1]; bL[j][1] = BsL[o1];
            }
            #pragma unroll
            for (int i = 0; i < 2; i++)
                #pragma unroll
                for (int j = 0; j < 4; j++) {
                    mma_tf32(acc[i][j], aL[i], bH[j]);   // lo*hi
                    mma_tf32(acc[i][j], aH[i], bL[j]);   // hi*lo
                    mma_tf32(acc[i][j], aH[i], bH[j]);   // hi*hi
                }
        }
        __syncthreads();
    }

    // ---- epilogue ----
    #pragma unroll
    for (int i = 0; i < 2; i++)
        #pragma unroll
        for (int j = 0; j < 4; j++) {
            const int r0 = m0 + wm + i * 16 + gid;
            const int c0 = n0 + wn + j * 8 + tig * 2;
            float2 v01 = make_float2(acc[i][j][0] * alpha, acc[i][j][1] * alpha);
            float2 v23 = make_float2(acc[i][j][2] * alpha, acc[i][j][3] * alpha);
            for (int r = 0; r < rep; r++) {
                *(float2*)&C[(size_t)r0 * N + c0 + (size_t)r * repStride] = v01;
                *(float2*)&C[(size_t)(r0 + 8) * N + c0 + (size_t)r * repStride] = v23;
            }
        }
}

// ---------------- softmax over rows of length 1024 ---------------------------
__global__ void softmax_rows(float* __restrict__ s)
{
    float* row = s + (size_t)blockIdx.x * SS;
    const int tid = threadIdx.x;
    __shared__ float red[256];
    float v[4];
    float m = -1e30f;
    #pragma unroll
    for (int i = 0; i < 4; i++) { v[i] = row[tid + i*256]; m = fmaxf(m, v[i]); }
    red[tid] = m; __syncthreads();
    for (int st = 128; st > 0; st >>= 1) {
        if (tid < st) red[tid] = fmaxf(red[tid], red[tid + st]);
        __syncthreads();
    }
    m = red[0]; __syncthreads();
    float sum = 0.f;
    #pragma unroll
    for (int i = 0; i < 4; i++) { v[i] = __expf(v[i] - m); sum += v[i]; }
    red[tid] = sum; __syncthreads();
    for (int st = 128; st > 0; st >>= 1) {
        if (tid < st) red[tid] += red[tid + st];
        __syncthreads();
    }
    const float inv = 1.f / red[0];
    #pragma unroll
    for (int i = 0; i < 4; i++) row[tid + i*256] = v[i] * inv;
}

// ---------------- y = a + (relu?)(b); partial column stats -------------------
__global__ void add_stats(const float* __restrict__ a, const float* __restrict__ b,
                          float* __restrict__ y, float* __restrict__ part, int relu)
{
    const int c = threadIdx.x;
    const int h = blockIdx.y;
    const int chunk = blockIdx.x;
    const size_t base = (size_t)h * BS * VV;
    float sum = 0.f, sq = 0.f;
    const int r0 = chunk * 128;
    for (int r = r0; r < r0 + 128; r++) {
        size_t idx = base + (size_t)r * VV + c;
        float bv = b[idx];
        if (relu) bv = fmaxf(bv, 0.f);
        float yv = a[idx] + bv;
        y[idx] = yv;
        sum += yv; sq += yv * yv;
    }
    size_t p = ((size_t)(h*NCH + chunk)*VV + c) * 2;
    part[p + 0] = sum;
    part[p + 1] = sq;
}

// ---------------- batchnorm normalize ---------------------------------------
__global__ void bn_norm(float* __restrict__ y, const float* __restrict__ part,
                        const float* __restrict__ gamma, const float* __restrict__ beta,
                        int gstride)
{
    const int c = threadIdx.x;
    const int h = blockIdx.y;
    const int chunk = blockIdx.x;
    const float* p = part + (size_t)h * NCH * VV * 2;
    float sum = 0.f, sq = 0.f;
    #pragma unroll
    for (int j = 0; j < NCH; j++) {
        sum += p[((size_t)j*VV + c)*2 + 0];
        sq  += p[((size_t)j*VV + c)*2 + 1];
    }
    const float mean = sum * (1.f / BS);
    const float var  = sq  * (1.f / BS) - mean * mean;
    const float inv  = rsqrtf(var + EPS);
    const float g = gamma[(size_t)h * gstride + c];
    const float b = beta [(size_t)h * gstride + c];
    const float sc = inv * g;
    const float sh = b - mean * sc;
    float* base = y + (size_t)h * BS * VV;
    const int r0 = chunk * 128;
    for (int r = r0; r < r0 + 128; r++) {
        size_t idx = (size_t)r * VV + c;
        base[idx] = base[idx] * sc + sh;
    }
}

// ---------------- [H][B*S][V] -> [B,S,H,V] -----------------------------------
__global__ void write_out(const float* __restrict__ net, float* __restrict__ out)
{
    const int h = blockIdx.y, row = blockIdx.x, c = threadIdx.x;
    out[((size_t)row * HH + h) * VV + c] =
        net[(size_t)h * BS * VV + (size_t)row * VV + c];
}

// ---------------- launcher ---------------------------------------------------
extern "C" void kernel_launch(void* const* d_in, const int* in_sizes, int n_in,
                              void* d_out, int out_size)
{
    const float* x     = (const float*)d_in[0];
    const float* W_in  = (const float*)d_in[1];
    const float* Wq    = (const float*)d_in[2];
    const float* Wk    = (const float*)d_in[3];
    const float* Wv    = (const float*)d_in[4];
    const float* Wd    = (const float*)d_in[5];
    const float* g1    = (const float*)d_in[6];
    const float* b1    = (const float*)d_in[7];
    const float* g2    = (const float*)d_in[8];
    const float* b2    = (const float*)d_in[9];
    float* out = (float*)d_out;

    float *net, *q, *k, *v, *scores, *attnout, *z, *part;
    cudaGetSymbolAddress((void**)&net,     g_net);
    cudaGetSymbolAddress((void**)&q,       g_q);
    cudaGetSymbolAddress((void**)&k,       g_k);
    cudaGetSymbolAddress((void**)&v,       g_v);
    cudaGetSymbolAddress((void**)&scores,  g_scores);
    cudaGetSymbolAddress((void**)&attnout, g_attnout);
    cudaGetSymbolAddress((void**)&z,       g_z);
    cudaGetSymbolAddress((void**)&part,    g_part);

    const int smem_bytes = SMEM_U32 * 4;   // 55296
    static int configured = 0;
    if (!configured) {
        cudaFuncSetAttribute(gemm_mma<0>, cudaFuncAttributeMaxDynamicSharedMemorySize, smem_bytes);
        cudaFuncSetAttribute(gemm_mma<1>, cudaFuncAttributeMaxDynamicSharedMemorySize, smem_bytes);
        configured = 1;
    }

    const float scale = 0.125f;   // KD^-0.5

    // net[h] = x @ W_in, replicated to all 8 heads
    gemm_mma<0><<<dim3(VV/GBN, BS/GBM, 1), 256, smem_bytes>>>(x, W_in, net, BS, VV, DIN,
                                                  0, 0, 0, 1.f, HH, (long long)BS*VV);

    for (int t = 0; t < TT; t++) {
        gemm_mma<0><<<dim3(KDIM/GBN, BS/GBM, HH), 256, smem_bytes>>>(net, Wq + (size_t)t*VV*KDIM, q,
            BS, KDIM, VV, (long long)BS*VV, (long long)TT*VV*KDIM, (long long)BS*KDIM, 1.f, 1, 0);
        gemm_mma<0><<<dim3(KDIM/GBN, BS/GBM, HH), 256, smem_bytes>>>(net, Wk + (size_t)t*VV*KDIM, k,
            BS, KDIM, VV, (long long)BS*VV, (long long)TT*VV*KDIM, (long long)BS*KDIM, 1.f, 1, 0);
        gemm_mma<0><<<dim3(VV/GBN, BS/GBM, HH), 256, smem_bytes>>>(net, Wv + (size_t)t*VV*VV, v,
            BS, VV, VV, (long long)BS*VV, (long long)TT*VV*VV, (long long)BS*VV, 1.f, 1, 0);

        // scores = scale * q @ k^T, batched over (h,b) = 32
        gemm_mma<1><<<dim3(SS/GBN, SS/GBM, HH*BB), 256, smem_bytes>>>(q, k, scores,
            SS, SS, KDIM, (long long)SS*KDIM, (long long)SS*KDIM, (long long)SS*SS, scale, 1, 0);

        softmax_rows<<<HH*BB*SS, 256>>>(scores);

        // attnout = scores @ v
        gemm_mma<0><<<dim3(VV/GBN, SS/GBM, HH*BB), 256, smem_bytes>>>(scores, v, attnout,
            SS, VV, SS, (long long)SS*SS, (long long)SS*VV, (long long)SS*VV, 1.f, 1, 0);

        // net = BN(net + attnout)
        add_stats<<<dim3(NCH, HH), 256>>>(net, attnout, net, part, 0);
        bn_norm<<<dim3(NCH, HH), 256>>>(net, part, g1 + (size_t)t*VV, b1 + (size_t)t*VV, TT*VV);

        // z = net @ Wd; net = BN(net + relu(z))
        gemm_mma<0><<<dim3(VV/GBN, BS/GBM, HH), 256, smem_bytes>>>(net, Wd + (size_t)t*VV*VV, z,
            BS, VV, VV, (long long)BS*VV, (long long)TT*VV*VV, (long long)BS*VV, 1.f, 1, 0);
        add_stats<<<dim3(NCH, HH), 256>>>(net, z, net, part, 1);
        bn_norm<<<dim3(NCH, HH), 256>>>(net, part, g2 + (size_t)t*VV, b2 + (size_t)t*VV, TT*VV);
    }

    write_out<<<dim3(BS, HH), 256>>>(net, out);
}